// round 2
// baseline (speedup 1.0000x reference)
#include <cuda_runtime.h>
#include <cstdint>

// CRF forward scan. One warp per batch; thread `lane` owns states lane and lane+32.
// alpha[j] <- feat[t,j] + c_j + mshift + log( sum_i exp(alpha[i]-mshift) * W[i][j] )
// W[i][j] = exp(trans[i][j] - c_j), c_j = max_i trans[i][j].
// mshift is the ONE-STEP-STALE warp max (LSE is shift-invariant; staleness only
// changes exponent range by the per-step drift <= ~14, safe in fp32).

#define TT 64
typedef unsigned long long u64;

__device__ float g_Wt[TT * TT];  // g_Wt[j*64 + i] = exp(trans[i][j] - c_j)
__device__ float g_c[TT];

__device__ __forceinline__ u64 pack2(float lo, float hi) {
    u64 r;
    asm("mov.b64 %0, {%1, %2};" : "=l"(r) : "f"(lo), "f"(hi));
    return r;
}
__device__ __forceinline__ void unpack2(u64 v, float& lo, float& hi) {
    asm("mov.b64 {%0, %1}, %2;" : "=f"(lo), "=f"(hi) : "l"(v));
}
__device__ __forceinline__ u64 ffma2(u64 a, u64 b, u64 c) {
    u64 d;
    asm("fma.rn.f32x2 %0, %1, %2, %3;" : "=l"(d) : "l"(a), "l"(b), "l"(c));
    return d;
}
__device__ __forceinline__ u64 fadd2(u64 a, u64 b) {
    u64 d;
    asm("add.rn.f32x2 %0, %1, %2;" : "=l"(d) : "l"(a), "l"(b));
    return d;
}

// ---------------------------------------------------------------------------
__global__ void crf_prep_kernel(const float* __restrict__ trans) {
    int j = threadIdx.x;
    float c = -3.402823466e+38f;
    #pragma unroll
    for (int i = 0; i < TT; i++) c = fmaxf(c, trans[i * TT + j]);
    g_c[j] = c;
    #pragma unroll
    for (int i = 0; i < TT; i++) g_Wt[j * TT + i] = __expf(trans[i * TT + j] - c);
}

// ---------------------------------------------------------------------------
__global__ void __launch_bounds__(32) crf_scan_kernel(
    const float* __restrict__ feats,   // [B, S, 64]
    const float* __restrict__ masks,   // [B, S]
    float* __restrict__ out,           // [B, 64]
    int Sdim)
{
    const int b    = blockIdx.x;
    const int lane = threadIdx.x;
    const int jA   = lane;
    const int jB   = lane + 32;

    __shared__ float s_v[2][TT];   // double-buffered exp(alpha - mshift)

    // W columns jA and jB in packed f32x2 registers (64 u64 = 128 regs).
    u64 wA[32], wB[32];
    {
        const float4* pa = reinterpret_cast<const float4*>(&g_Wt[jA * TT]);
        const float4* pb = reinterpret_cast<const float4*>(&g_Wt[jB * TT]);
        #pragma unroll
        for (int q = 0; q < 16; q++) {
            float4 fa = pa[q];
            wA[2 * q]     = pack2(fa.x, fa.y);
            wA[2 * q + 1] = pack2(fa.z, fa.w);
            float4 fbq = pb[q];
            wB[2 * q]     = pack2(fbq.x, fbq.y);
            wB[2 * q + 1] = pack2(fbq.z, fbq.w);
        }
    }
    const float cA = g_c[jA];
    const float cB = g_c[jB];

    const float* fb = feats + (size_t)b * Sdim * TT;
    const float* mb = masks + (size_t)b * Sdim;

    float aA = fb[jA];   // alpha0
    float aB = fb[jB];

    // Exact initial shift.
    float m = fmaxf(aA, aB);
    #pragma unroll
    for (int o = 16; o > 0; o >>= 1)
        m = fmaxf(m, __shfl_xor_sync(0xffffffffu, m, o));

    // Distance-2 prefetch of feats/mask.
    const int t1 = (Sdim > 1) ? 1 : 0;
    const int t2 = (Sdim > 2) ? 2 : (Sdim - 1);
    float f1A = fb[(size_t)t1 * TT + jA], f1B = fb[(size_t)t1 * TT + jB], mk1 = mb[t1];
    float f2A = fb[(size_t)t2 * TT + jA], f2B = fb[(size_t)t2 * TT + jB], mk2 = mb[t2];

    int buf = 0;
    for (int t = 1; t < Sdim; t++) {
        // Prefetch step t+2.
        const int tp = (t + 2 < Sdim) ? (t + 2) : (Sdim - 1);
        const float f3A = fb[(size_t)tp * TT + jA];
        const float f3B = fb[(size_t)tp * TT + jB];
        const float mk3 = mb[tp];

        // v = exp(alpha - stale max) — starts immediately, no reduction in front.
        const float vA = __expf(aA - m);
        const float vB = __expf(aB - m);
        s_v[buf][jA] = vA;
        s_v[buf][jB] = vB;

        // Next step's shift: warp max of CURRENT alpha (overlaps the matvec).
        float mn = fmaxf(aA, aB);
        #pragma unroll
        for (int o = 16; o > 0; o >>= 1)
            mn = fmaxf(mn, __shfl_xor_sync(0xffffffffu, mn, o));

        __syncwarp();

        // Matvec: P_j = sum_i v_i * W[i][j] for both columns (packed f32x2).
        const float4* vp = reinterpret_cast<const float4*>(s_v[buf]);
        u64 accA[4] = {0ull, 0ull, 0ull, 0ull};
        u64 accB[4] = {0ull, 0ull, 0ull, 0ull};
        #pragma unroll
        for (int q = 0; q < 16; q++) {
            float4 f = vp[q];                       // broadcast ld.shared.v4
            u64 v01 = pack2(f.x, f.y);
            u64 v23 = pack2(f.z, f.w);
            accA[(2 * q) & 3]     = ffma2(v01, wA[2 * q],     accA[(2 * q) & 3]);
            accA[(2 * q + 1) & 3] = ffma2(v23, wA[2 * q + 1], accA[(2 * q + 1) & 3]);
            accB[(2 * q) & 3]     = ffma2(v01, wB[2 * q],     accB[(2 * q) & 3]);
            accB[(2 * q + 1) & 3] = ffma2(v23, wB[2 * q + 1], accB[(2 * q + 1) & 3]);
        }
        u64 sA = fadd2(fadd2(accA[0], accA[1]), fadd2(accA[2], accA[3]));
        u64 sB = fadd2(fadd2(accB[0], accB[1]), fadd2(accB[2], accB[3]));
        float pAl, pAh, pBl, pBh;
        unpack2(sA, pAl, pAh);
        unpack2(sB, pBl, pBh);
        const float PA = pAl + pAh;
        const float PB = pBl + pBh;

        const float naA = f1A + cA + m + __logf(PA);
        const float naB = f1B + cB + m + __logf(PB);
        aA = naA * mk1 + aA * (1.0f - mk1);
        aB = naB * mk1 + aB * (1.0f - mk1);

        m = mn;                                    // one-step-stale shift
        f1A = f2A; f1B = f2B; mk1 = mk2;
        f2A = f3A; f2B = f3B; mk2 = mk3;
        buf ^= 1;
    }

    out[(size_t)b * TT + jA] = aA;
    out[(size_t)b * TT + jB] = aB;
}

// ---------------------------------------------------------------------------
extern "C" void kernel_launch(void* const* d_in, const int* in_sizes, int n_in,
                              void* d_out, int out_size) {
    const float* feats = (const float*)d_in[0];
    const float* masks = (const float*)d_in[1];
    const float* trans = (const float*)d_in[2];
    float* out = (float*)d_out;

    const int Bn   = out_size / TT;
    const int Sdim = in_sizes[0] / (Bn * TT);

    crf_prep_kernel<<<1, TT>>>(trans);
    crf_scan_kernel<<<Bn, 32>>>(feats, masks, out, Sdim);
}

// round 3
// speedup vs baseline: 2.5080x; 2.5080x over previous
#include <cuda_runtime.h>
#include <cstdint>

// CRF forward scan, B blocks x 64 threads (thread j = state j).
// alpha[j] <- feat[t,j] + c_j + m + log( sum_i exp(alpha[i]-m) * W[i][j] )
// W[i][j] = exp(trans[i][j]-c_j), c_j = max_i trans[i][j].
// m is a stale-by-2 block max (LSE shift-invariant; drift tiny vs fp32 range).
// feats/masks staged 16 steps at a time into smem via cp.async (3-buf pipeline).

#define TT 64
#define CHUNK 16
typedef unsigned long long u64;

__device__ float g_Wt[TT * TT];  // g_Wt[j*64+i] = exp(trans[i][j]-c_j)
__device__ float g_c[TT];

__device__ __forceinline__ u64 pack2(float lo, float hi) {
    u64 r; asm("mov.b64 %0, {%1, %2};" : "=l"(r) : "f"(lo), "f"(hi)); return r;
}
__device__ __forceinline__ void unpack2(u64 v, float& lo, float& hi) {
    asm("mov.b64 {%0, %1}, %2;" : "=f"(lo), "=f"(hi) : "l"(v));
}
__device__ __forceinline__ u64 ffma2(u64 a, u64 b, u64 c) {
    u64 d; asm("fma.rn.f32x2 %0, %1, %2, %3;" : "=l"(d) : "l"(a), "l"(b), "l"(c)); return d;
}
__device__ __forceinline__ u64 fadd2(u64 a, u64 b) {
    u64 d; asm("add.rn.f32x2 %0, %1, %2;" : "=l"(d) : "l"(a), "l"(b)); return d;
}
__device__ __forceinline__ uint32_t smem_u32(const void* p) {
    uint32_t a;
    asm("{ .reg .u64 t; cvta.to.shared.u64 t, %1; cvt.u32.u64 %0, t; }" : "=r"(a) : "l"(p));
    return a;
}

// ---------------------------------------------------------------------------
__global__ void crf_prep_kernel(const float* __restrict__ trans) {
    int j = threadIdx.x;
    float c = -3.402823466e+38f;
    #pragma unroll
    for (int i = 0; i < TT; i++) c = fmaxf(c, trans[i * TT + j]);
    g_c[j] = c;
    #pragma unroll
    for (int i = 0; i < TT; i++) g_Wt[j * TT + i] = __expf(trans[i * TT + j] - c);
}

// ---------------------------------------------------------------------------
__global__ void __launch_bounds__(64) crf_scan_kernel(
    const float* __restrict__ feats,   // [B, S, 64]
    const float* __restrict__ masks,   // [B, S]
    float* __restrict__ out,           // [B, 64]
    int Sdim)
{
    const int b    = blockIdx.x;
    const int j    = threadIdx.x;
    const int warp = j >> 5;
    const int lane = j & 31;

    __shared__ float s_feat[3][CHUNK][TT];   // 12 KB staged feats
    __shared__ float s_mask[3][CHUNK];
    __shared__ float s_v[2][TT];             // exp(alpha - m), double buffered
    __shared__ float s_wm[4][2];             // per-warp maxima ring

    // W column j into packed f32x2 registers.
    u64 w[32];
    {
        const float4* wp = reinterpret_cast<const float4*>(&g_Wt[j * TT]);
        #pragma unroll
        for (int q = 0; q < 16; q++) {
            float4 f = wp[q];
            w[2 * q]     = pack2(f.x, f.y);
            w[2 * q + 1] = pack2(f.z, f.w);
        }
    }
    const float cj = g_c[j];

    const float* fbp = feats + (size_t)b * Sdim * TT;
    const float* mbp = masks + (size_t)b * Sdim;
    const uint32_t feat_s0 = smem_u32(&s_feat[0][0][0]);

    const int NC = (Sdim + CHUNK - 1) / CHUNK;

    // ---- stage chunk c into buffer c%3 (feats via cp.async, masks via LDG/STS)
    auto stage = [&](int c) {
        const int base = c * CHUNK;
        const int bufo = (c % 3) * CHUNK * TT;
        #pragma unroll
        for (int q = 0; q < 4; q++) {
            int g   = q * 64 + j;          // 16B granule id, 0..255
            int row = g >> 4;
            int col = (g & 15) << 2;
            int gr  = base + row; if (gr >= Sdim) gr = Sdim - 1;
            const float* src = fbp + (size_t)gr * TT + col;
            uint32_t dst = feat_s0 + (uint32_t)(bufo + row * TT + col) * 4u;
            asm volatile("cp.async.cg.shared.global [%0], [%1], 16;" :: "r"(dst), "l"(src));
        }
        if (j < CHUNK) {
            int gr = base + j; if (gr >= Sdim) gr = Sdim - 1;
            s_mask[c % 3][j] = mbp[gr];
        }
    };

    // Prologue: chunks 0 and 1 in flight; chunk 0 resident before alpha init.
    stage(0);
    asm volatile("cp.async.commit_group;");
    if (NC > 1) stage(1);
    asm volatile("cp.async.commit_group;");
    asm volatile("cp.async.wait_group 1;");
    __syncthreads();

    float alpha = s_feat[0][0][j];           // alpha0 = feats[b,0,:]

    // Exact initial shift + seed the wm ring for step 1's read.
    {
        float wmx = alpha;
        #pragma unroll
        for (int o = 16; o > 0; o >>= 1)
            wmx = fmaxf(wmx, __shfl_xor_sync(0xffffffffu, wmx, o));
        if (lane == 0) s_wm[1][warp] = wmx;
    }
    __syncthreads();
    float m = fmaxf(s_wm[1][0], s_wm[1][1]);

    for (int c = 0; c < NC; c++) {
        if (c > 0) asm volatile("cp.async.wait_group 1;");  // chunk c resident
        if (c + 2 < NC) stage(c + 2);
        asm volatile("cp.async.commit_group;");             // uniform group count
        __syncthreads();

        #pragma unroll
        for (int r = 0; r < CHUNK; r++) {
            const int t = c * CHUNK + r;
            if (t >= 1 && t < Sdim) {                       // uniform guard
                // exp with stale shift, publish v
                const float v = __expf(alpha - m);
                s_v[r & 1][j] = v;
                __syncthreads();

                // matvec P_j = sum_i v_i * W[i][j]
                const float4* vp = reinterpret_cast<const float4*>(s_v[r & 1]);
                u64 acc[4] = {0ull, 0ull, 0ull, 0ull};
                #pragma unroll
                for (int q = 0; q < 16; q++) {
                    float4 f = vp[q];
                    acc[(2 * q) & 3]     = ffma2(pack2(f.x, f.y), w[2 * q],     acc[(2 * q) & 3]);
                    acc[(2 * q + 1) & 3] = ffma2(pack2(f.z, f.w), w[2 * q + 1], acc[(2 * q + 1) & 3]);
                }
                u64 s2 = fadd2(fadd2(acc[0], acc[1]), fadd2(acc[2], acc[3]));
                float lo, hi; unpack2(s2, lo, hi);
                const float P = lo + hi;

                // shift for step t+1 (written at step t-1); overlap wm tree w/ matvec
                const float mnext = fmaxf(s_wm[r & 3][0], s_wm[r & 3][1]);
                float wmx = alpha;
                #pragma unroll
                for (int o = 16; o > 0; o >>= 1)
                    wmx = fmaxf(wmx, __shfl_xor_sync(0xffffffffu, wmx, o));
                if (lane == 0) s_wm[(r + 1) & 3][warp] = wmx;

                const float ft = s_feat[c % 3][r][j];
                const float mk = s_mask[c % 3][r];
                const float na = ft + cj + m + __logf(P);
                alpha = na * mk + alpha * (1.0f - mk);
                m = mnext;
            }
        }
    }

    out[(size_t)b * TT + j] = alpha;
}

// ---------------------------------------------------------------------------
extern "C" void kernel_launch(void* const* d_in, const int* in_sizes, int n_in,
                              void* d_out, int out_size) {
    const float* feats = (const float*)d_in[0];
    const float* masks = (const float*)d_in[1];
    const float* trans = (const float*)d_in[2];
    float* out = (float*)d_out;

    const int Bn   = out_size / TT;
    const int Sdim = in_sizes[0] / (Bn * TT);

    crf_prep_kernel<<<1, TT>>>(trans);
    crf_scan_kernel<<<Bn, TT>>>(feats, masks, out, Sdim);
}